// round 6
// baseline (speedup 1.0000x reference)
#include <cuda_runtime.h>
#include <cuda_bf16.h>
#include <cstdint>

#define D 64
#define TILE_M 128
#define NREP 64
#define MAX_N 100000

// ---------------- scratch (device globals) ----------------
__device__ float g_neigh[MAX_N * D];
__device__ float g_sum[2][NREP][D];
__device__ float g_sq[2][NREP][D];
__device__ __align__(16) float g_mean[2][D];
__device__ __align__(16) float g_rstd[2][D];
// 4 swizzled bf16 W tiles [k][n] (64x64, 128B rows): 0=W1hi 1=W1lo 2=W2hi 3=W2lo
__device__ __align__(16) char g_Wb[4 * 8192];

// ---------------- helpers ----------------
__device__ __forceinline__ uint32_t s2u(const void* p) {
    uint32_t a;
    asm("{ .reg .u64 t; cvta.to.shared.u64 t, %1; cvt.u32.u64 %0, t; }" : "=r"(a) : "l"(p));
    return a;
}
__device__ __forceinline__ uint32_t sw128(uint32_t off) {
    return off ^ ((off >> 3) & 0x70);
}
__device__ __forceinline__ uint32_t pack_bf16(float lo, float hi) {
    uint32_t r;
    asm("cvt.rn.bf16x2.f32 %0, %1, %2;" : "=r"(r) : "f"(hi), "f"(lo));
    return r;
}
// split two fp32 into bf16 hi-word and lo-word (residual) pairs
__device__ __forceinline__ void split2(float a, float b, uint32_t& hw, uint32_t& lw) {
    __nv_bfloat16 ha = __float2bfloat16_rn(a), hb = __float2bfloat16_rn(b);
    hw = ((uint32_t)__bfloat16_as_ushort(hb) << 16) | __bfloat16_as_ushort(ha);
    lw = pack_bf16(a - __bfloat162float(ha), b - __bfloat162float(hb));
}
__device__ __forceinline__ void ldsm4(uint32_t addr, uint32_t* r) {
    asm volatile("ldmatrix.sync.aligned.m8n8.x4.shared.b16 {%0,%1,%2,%3}, [%4];"
                 : "=r"(r[0]), "=r"(r[1]), "=r"(r[2]), "=r"(r[3]) : "r"(addr));
}
__device__ __forceinline__ void ldsm4t(uint32_t addr, uint32_t* r) {
    asm volatile("ldmatrix.sync.aligned.m8n8.x4.trans.shared.b16 {%0,%1,%2,%3}, [%4];"
                 : "=r"(r[0]), "=r"(r[1]), "=r"(r[2]), "=r"(r[3]) : "r"(addr));
}
__device__ __forceinline__ void mma16816(float* c, const uint32_t* a, const uint32_t* b) {
    asm volatile(
        "mma.sync.aligned.m16n8k16.row.col.f32.bf16.bf16.f32 "
        "{%0,%1,%2,%3}, {%4,%5,%6,%7}, {%8,%9}, {%0,%1,%2,%3};"
        : "+f"(c[0]), "+f"(c[1]), "+f"(c[2]), "+f"(c[3])
        : "r"(a[0]), "r"(a[1]), "r"(a[2]), "r"(a[3]), "r"(b[0]), "r"(b[1]));
}

// ---------------- K0: zero scratch + build split/swizzled W [k][n] ----------------
__global__ void zero_kernel(const float* __restrict__ W1, const float* __restrict__ W2) {
    int tid = blockIdx.x * blockDim.x + threadIdx.x;
    int stride = gridDim.x * blockDim.x;
    float4* p = (float4*)g_neigh;
    const int n4 = MAX_N * D / 4;
    for (int i = tid; i < n4; i += stride) p[i] = make_float4(0.f, 0.f, 0.f, 0.f);
    float* s = &g_sum[0][0][0];
    float* q = &g_sq[0][0][0];
    const int ns = 2 * NREP * D;
    for (int i = tid; i < ns; i += stride) { s[i] = 0.f; q[i] = 0.f; }
    for (int i = tid; i < 4 * 4096; i += stride) {
        int t = i >> 12;          // 0=W1hi 1=W1lo 2=W2hi 3=W2lo
        int idx = i & 4095;
        int k = idx >> 6;
        int n = idx & 63;
        const float* W = (t >= 2) ? W2 : W1;
        float w = __ldg(&W[k * D + n]);
        __nv_bfloat16 hv = __float2bfloat16_rn(w);
        __nv_bfloat16 val = (t & 1) ? __float2bfloat16_rn(w - __bfloat162float(hv)) : hv;
        *(__nv_bfloat16*)(g_Wb + t * 8192 + sw128(k * 128 + n * 2)) = val;
    }
}

// ---------------- K1: scatter-sum ----------------
__global__ void scatter_kernel(const float* __restrict__ h,
                               const int* __restrict__ src,
                               const int* __restrict__ dst, int E) {
    int idx = blockIdx.x * blockDim.x + threadIdx.x;
    int total = E * 16;
    if (idx >= total) return;
    int e = idx >> 4;
    int c = idx & 15;
    int s = __ldg(&src[e]);
    int d = __ldg(&dst[e]);
    float4 v = __ldg((const float4*)(h + (size_t)s * D) + c);
    float* p = g_neigh + (size_t)d * D + c * 4;
    asm volatile("red.global.add.v4.f32 [%0], {%1, %2, %3, %4};"
                 :: "l"(p), "f"(v.x), "f"(v.y), "f"(v.z), "f"(v.w) : "memory");
}

// SMEM layout (dynamic)
#define SM_AHI 0
#define SM_ALO 16384
#define SM_W 32768
#define SM_B1 65536
#define SM_B2 65792
#define SM_STAT 66048
#define SMEM_BYTES 66560

// one GEMM layer: acc += split3( A(128x64) * W(64x64) ), per-warp 32 rows
__device__ __forceinline__ void gemm_mma(uint32_t aHi, uint32_t aLo,
                                         uint32_t wHi, uint32_t wLo,
                                         int mrow, int lane, float acc[2][8][4]) {
    int lr = lane & 15;
    int lc = lane >> 4;
#pragma unroll
    for (int kc = 0; kc < 4; ++kc) {
        uint32_t ah[2][4], al[2][4];
#pragma unroll
        for (int mt = 0; mt < 2; ++mt) {
            uint32_t off = sw128((mrow + mt * 16 + lr) * 128 + kc * 32 + lc * 16);
            ldsm4(aHi + off, ah[mt]);
            ldsm4(aLo + off, al[mt]);
        }
        uint32_t bh[8][2], bl[8][2];
#pragma unroll
        for (int nt2 = 0; nt2 < 4; ++nt2) {
            uint32_t off = sw128((kc * 16 + lr) * 128 + (nt2 * 16 + lc * 8) * 2);
            uint32_t t4[4];
            ldsm4t(wHi + off, t4);
            bh[2 * nt2][0] = t4[0]; bh[2 * nt2][1] = t4[1];
            bh[2 * nt2 + 1][0] = t4[2]; bh[2 * nt2 + 1][1] = t4[3];
            ldsm4t(wLo + off, t4);
            bl[2 * nt2][0] = t4[0]; bl[2 * nt2][1] = t4[1];
            bl[2 * nt2 + 1][0] = t4[2]; bl[2 * nt2 + 1][1] = t4[3];
        }
#pragma unroll
        for (int mt = 0; mt < 2; ++mt)
#pragma unroll
            for (int nt = 0; nt < 8; ++nt) {
                mma16816(acc[mt][nt], ah[mt], bh[nt]);
                mma16816(acc[mt][nt], ah[mt], bl[nt]);
                mma16816(acc[mt][nt], al[mt], bh[nt]);
            }
    }
}

// ---------------- K2: HMMA MLP (+fused column stats), nodes then edges ----------------
__global__ void __launch_bounds__(128, 2)
mlp_mma_kernel(const float* __restrict__ hin, const float* __restrict__ ein,
               const float* __restrict__ epsp,
               const float* __restrict__ b1, const float* __restrict__ b2,
               float* __restrict__ out, int N, int E, int nblk) {
    extern __shared__ char smem[];
    uint32_t smem0 = s2u(smem);
    int tid = threadIdx.x;
    int wid = tid >> 5;
    int lane = tid & 31;

    int target, row0, M;
    const float* xin;
    float* yout;
    if (blockIdx.x < nblk) {
        target = 0; row0 = blockIdx.x * TILE_M; M = N; xin = hin; yout = out;
    } else {
        target = 1; row0 = (blockIdx.x - nblk) * TILE_M; M = E; xin = ein;
        yout = out + (size_t)N * D;
    }

    // weights (32KB) + biases + zero stats
    {
        const float4* src = (const float4*)g_Wb;
        float4* dst = (float4*)(smem + SM_W);
        for (int i = tid; i < 2048; i += 128) dst[i] = src[i];
    }
    if (tid < 64) {
        ((float*)(smem + SM_B1))[tid] = __ldg(&b1[tid]);
        ((float*)(smem + SM_B2))[tid] = __ldg(&b2[tid]);
        ((float*)(smem + SM_STAT))[tid] = 0.f;
        ((float*)(smem + SM_STAT))[tid + 64] = 0.f;
    }

    // fill A tile (bf16 hi/lo, swizzled)
    float epsv = (target == 0) ? (1.f + __ldg(&epsp[0])) : 1.f;
    for (int ch = tid; ch < TILE_M * 16; ch += 128) {
        int r = ch >> 4;
        int c4 = ch & 15;
        int gr = row0 + r;
        float4 v = make_float4(0.f, 0.f, 0.f, 0.f);
        if (gr < M) {
            if (target == 0) {
                float4 a = __ldg((const float4*)(xin + (size_t)gr * D) + c4);
                float4 n = *((const float4*)(g_neigh + (size_t)gr * D) + c4);
                v.x = fmaf(epsv, a.x, n.x);
                v.y = fmaf(epsv, a.y, n.y);
                v.z = fmaf(epsv, a.z, n.z);
                v.w = fmaf(epsv, a.w, n.w);
            } else {
                v = __ldg((const float4*)(xin + (size_t)gr * D) + c4);
            }
        }
        uint32_t h0, l0, h1, l1;
        split2(v.x, v.y, h0, l0);
        split2(v.z, v.w, h1, l1);
        uint32_t o0 = sw128(r * 128 + c4 * 8);
        *(uint2*)(smem + SM_AHI + o0) = make_uint2(h0, h1);
        *(uint2*)(smem + SM_ALO + o0) = make_uint2(l0, l1);
    }
    __syncthreads();

    int mrow = wid * 32;
    uint32_t aHi = smem0 + SM_AHI, aLo = smem0 + SM_ALO;
    float acc[2][8][4];

    // ---- layer 1 ----
#pragma unroll
    for (int mt = 0; mt < 2; ++mt)
#pragma unroll
        for (int nt = 0; nt < 8; ++nt)
#pragma unroll
            for (int i = 0; i < 4; ++i) acc[mt][nt][i] = 0.f;
    gemm_mma(aHi, aLo, smem0 + SM_W, smem0 + SM_W + 8192, mrow, lane, acc);

    // ---- transition: relu+b1, re-split into A (own rows only; no block sync) ----
    {
        const float* b1s = (const float*)(smem + SM_B1);
#pragma unroll
        for (int mt = 0; mt < 2; ++mt) {
            int r = mrow + mt * 16 + (lane >> 2);
#pragma unroll
            for (int nt = 0; nt < 8; ++nt) {
                int c = nt * 8 + (lane & 3) * 2;
                float2 bb = *(const float2*)(b1s + c);
                float t0 = fmaxf(acc[mt][nt][0] + bb.x, 0.f);
                float t1 = fmaxf(acc[mt][nt][1] + bb.y, 0.f);
                float t2 = fmaxf(acc[mt][nt][2] + bb.x, 0.f);
                float t3 = fmaxf(acc[mt][nt][3] + bb.y, 0.f);
                uint32_t hw, lw;
                split2(t0, t1, hw, lw);
                uint32_t o = sw128(r * 128 + c * 2);
                *(uint32_t*)(smem + SM_AHI + o) = hw;
                *(uint32_t*)(smem + SM_ALO + o) = lw;
                split2(t2, t3, hw, lw);
                o = sw128((r + 8) * 128 + c * 2);
                *(uint32_t*)(smem + SM_AHI + o) = hw;
                *(uint32_t*)(smem + SM_ALO + o) = lw;
            }
        }
    }
    __syncwarp();

    // ---- layer 2 ----
#pragma unroll
    for (int mt = 0; mt < 2; ++mt)
#pragma unroll
        for (int nt = 0; nt < 8; ++nt)
#pragma unroll
            for (int i = 0; i < 4; ++i) acc[mt][nt][i] = 0.f;
    gemm_mma(aHi, aLo, smem0 + SM_W + 16384, smem0 + SM_W + 24576, mrow, lane, acc);

    // ---- epilogue: y = acc + b2, store, fused column stats ----
    {
        const float* b2s = (const float*)(smem + SM_B2);
        float cs[16], cq[16];
#pragma unroll
        for (int i = 0; i < 16; ++i) { cs[i] = 0.f; cq[i] = 0.f; }
#pragma unroll
        for (int mt = 0; mt < 2; ++mt) {
            int r0g = row0 + mrow + mt * 16 + (lane >> 2);
#pragma unroll
            for (int half = 0; half < 2; ++half) {
                int gr = r0g + half * 8;
                if (gr >= M) continue;
                float* orow = yout + (size_t)gr * D;
#pragma unroll
                for (int nt = 0; nt < 8; ++nt) {
                    int c = nt * 8 + (lane & 3) * 2;
                    float2 bb = *(const float2*)(b2s + c);
                    float y0 = acc[mt][nt][half * 2 + 0] + bb.x;
                    float y1 = acc[mt][nt][half * 2 + 1] + bb.y;
                    *(float2*)(orow + c) = make_float2(y0, y1);
                    cs[nt * 2 + 0] += y0; cq[nt * 2 + 0] += y0 * y0;
                    cs[nt * 2 + 1] += y1; cq[nt * 2 + 1] += y1 * y1;
                }
            }
        }
        float* ss = (float*)(smem + SM_STAT);
        float* sq = ss + 64;
#pragma unroll
        for (int nt = 0; nt < 8; ++nt) {
            int c = nt * 8 + (lane & 3) * 2;
            atomicAdd(&ss[c], cs[nt * 2 + 0]);
            atomicAdd(&ss[c + 1], cs[nt * 2 + 1]);
            atomicAdd(&sq[c], cq[nt * 2 + 0]);
            atomicAdd(&sq[c + 1], cq[nt * 2 + 1]);
        }
    }
    __syncthreads();
    if (tid < 64) {
        int rep = blockIdx.x & (NREP - 1);
        float* ss = (float*)(smem + SM_STAT);
        atomicAdd(&g_sum[target][rep][tid], ss[tid]);
        atomicAdd(&g_sq[target][rep][tid], ss[tid + 64]);
    }
}

// ---------------- K3: finalize mean / rstd ----------------
__global__ void stats_kernel(int N, int E) {
    int t = threadIdx.x;
    int target = t >> 6;
    int c = t & 63;
    float s = 0.f, q = 0.f;
#pragma unroll
    for (int r = 0; r < NREP; ++r) { s += g_sum[target][r][c]; q += g_sq[target][r][c]; }
    float cnt = target ? (float)E : (float)N;
    float m = s / cnt;
    float var = q / cnt - m * m;
    g_mean[target][c] = m;
    g_rstd[target][c] = rsqrtf(var + 1e-5f);
}

// ---------------- K4/K5: normalize + relu + residual ----------------
__global__ void apply_kernel(const float* __restrict__ res,
                             const float* __restrict__ gamma,
                             const float* __restrict__ beta,
                             float* __restrict__ y, int M, int target) {
    int idx = blockIdx.x * blockDim.x + threadIdx.x;
    int total = M * 16;
    if (idx >= total) return;
    int r = idx >> 4;
    int c4 = idx & 15;
    size_t off = (size_t)r * D + c4 * 4;
    float4 v = *(float4*)(y + off);
    float4 rs = __ldg((const float4*)res + (off >> 2));
    float4 g = __ldg((const float4*)gamma + c4);
    float4 b = __ldg((const float4*)beta + c4);
    int c = c4 * 4;
    float4 m = *(const float4*)&g_mean[target][c];
    float4 sd = *(const float4*)&g_rstd[target][c];
    float4 o;
    o.x = rs.x + fmaxf(g.x * (v.x - m.x) * sd.x + b.x, 0.f);
    o.y = rs.y + fmaxf(g.y * (v.y - m.y) * sd.y + b.y, 0.f);
    o.z = rs.z + fmaxf(g.z * (v.z - m.z) * sd.z + b.z, 0.f);
    o.w = rs.w + fmaxf(g.w * (v.w - m.w) * sd.w + b.w, 0.f);
    *(float4*)(y + off) = o;
}

// ---------------- launcher ----------------
extern "C" void kernel_launch(void* const* d_in, const int* in_sizes, int n_in,
                              void* d_out, int out_size) {
    const float* h   = (const float*)d_in[0];
    const float* e   = (const float*)d_in[1];
    const int*   src = (const int*)d_in[2];
    const int*   dst = (const int*)d_in[3];
    const float* eps = (const float*)d_in[4];
    const float* W1  = (const float*)d_in[5];
    const float* b1  = (const float*)d_in[6];
    const float* W2  = (const float*)d_in[7];
    const float* b2  = (const float*)d_in[8];
    const float* gh  = (const float*)d_in[9];
    const float* bh  = (const float*)d_in[10];
    const float* ge  = (const float*)d_in[11];
    const float* be  = (const float*)d_in[12];

    int N = in_sizes[0] / D;
    int E = in_sizes[1] / D;
    float* out_h = (float*)d_out;
    float* out_e = out_h + (size_t)N * D;

    cudaFuncSetAttribute(mlp_mma_kernel, cudaFuncAttributeMaxDynamicSharedMemorySize, SMEM_BYTES);

    zero_kernel<<<1024, 256>>>(W1, W2);
    scatter_kernel<<<(E * 16 + 255) / 256, 256>>>(h, src, dst, E);

    int nblk = (N + TILE_M - 1) / TILE_M;
    int eblk = (E + TILE_M - 1) / TILE_M;
    mlp_mma_kernel<<<nblk + eblk, 128, SMEM_BYTES>>>(h, e, eps, b1, b2, out_h, N, E, nblk);

    stats_kernel<<<1, 128>>>(N, E);

    apply_kernel<<<(N * 16 + 255) / 256, 256>>>(h, gh, bh, out_h, N, 0);
    apply_kernel<<<(E * 16 + 255) / 256, 256>>>(e, ge, be, out_e, E, 1);
}

// round 7
// speedup vs baseline: 1.7492x; 1.7492x over previous
#include <cuda_runtime.h>
#include <cuda_bf16.h>
#include <cstdint>

#define D 64
#define CH 64              // rows per pipeline chunk
#define TILE 512           // rows per CTA
#define NSTEP (TILE / CH)
#define TS 65              // row-array stride in u64 (de-conflicts STS)
#define NREP 64
#define MAX_N 100000

// ---------------- scratch (device globals) ----------------
__device__ float g_neigh[MAX_N * D];
__device__ float g_sum[2][NREP][D];
__device__ float g_sq[2][NREP][D];
__device__ __align__(16) float g_mean[2][D];
__device__ __align__(16) float g_rstd[2][D];
// k-paired weights: g_Wp[layer][kp][c] = (W[2kp][c], W[2kp+1][c])
__device__ unsigned long long g_Wp[2][32][64];

// ---------------- packed fp32x2 helpers ----------------
__device__ __forceinline__ unsigned long long pack64(float lo, float hi) {
    unsigned long long r;
    asm("mov.b64 %0, {%1, %2};" : "=l"(r) : "f"(lo), "f"(hi));
    return r;
}
__device__ __forceinline__ void unpack2(unsigned long long v, float& lo, float& hi) {
    asm("mov.b64 {%0, %1}, %2;" : "=f"(lo), "=f"(hi) : "l"(v));
}
__device__ __forceinline__ unsigned long long fma2(unsigned long long a,
                                                   unsigned long long b,
                                                   unsigned long long c) {
    unsigned long long d;
    asm("fma.rn.f32x2 %0, %1, %2, %3;" : "=l"(d) : "l"(a), "l"(b), "l"(c));
    return d;
}

// ---------------- K0: zero scratch + build k-paired W ----------------
__global__ void zero_kernel(const float* __restrict__ W1, const float* __restrict__ W2) {
    int tid = blockIdx.x * blockDim.x + threadIdx.x;
    int stride = gridDim.x * blockDim.x;
    float4* p = (float4*)g_neigh;
    const int n4 = MAX_N * D / 4;
    for (int i = tid; i < n4; i += stride) p[i] = make_float4(0.f, 0.f, 0.f, 0.f);
    float* s = &g_sum[0][0][0];
    float* q = &g_sq[0][0][0];
    const int ns = 2 * NREP * D;
    for (int i = tid; i < ns; i += stride) { s[i] = 0.f; q[i] = 0.f; }
    for (int i = tid; i < 2 * 32 * 64; i += stride) {
        int layer = i >> 11;
        int kp = (i >> 6) & 31;
        int c = i & 63;
        const float* W = layer ? W2 : W1;
        g_Wp[layer][kp][c] = pack64(__ldg(&W[(2 * kp) * D + c]),
                                    __ldg(&W[(2 * kp + 1) * D + c]));
    }
}

// ---------------- K1: scatter-sum  neigh[dst] += h[src] ----------------
__global__ void scatter_kernel(const float* __restrict__ h,
                               const int* __restrict__ src,
                               const int* __restrict__ dst, int E) {
    int idx = blockIdx.x * blockDim.x + threadIdx.x;
    int total = E * 16;
    if (idx >= total) return;
    int e = idx >> 4;
    int c = idx & 15;
    int s = __ldg(&src[e]);
    int d = __ldg(&dst[e]);
    float4 v = __ldg((const float4*)(h + (size_t)s * D) + c);
    float* p = g_neigh + (size_t)d * D + c * 4;
    asm volatile("red.global.add.v4.f32 [%0], {%1, %2, %3, %4};"
                 :: "l"(p), "f"(v.x), "f"(v.y), "f"(v.z), "f"(v.w) : "memory");
}

// smem: xs[2][32*TS] u64  +  ts[2][32*TS] u64
#define SMEM_BYTES (4 * 32 * TS * 8)

// ---------------- K2: weight-stationary warp-specialized MLP ----------------
__global__ void __launch_bounds__(256, 1)
mlp_ws_kernel(const float* __restrict__ hin, const float* __restrict__ ein,
              const float* __restrict__ epsp,
              const float* __restrict__ b1, const float* __restrict__ b2,
              float* __restrict__ out, int N, int E, int nblk) {
    extern __shared__ unsigned long long smem[];
    unsigned long long* xs = smem;                 // [2][32*TS]
    unsigned long long* ts = smem + 2 * 32 * TS;   // [2][32*TS]

    int tid = threadIdx.x;
    int wid = tid >> 5;
    int lane = tid & 31;
    int isL2 = wid >> 2;       // warps 0-3: layer1, warps 4-7: layer2
    int wsub = wid & 3;

    int target, row0, M;
    const float* xin;
    float* yout;
    if (blockIdx.x < nblk) {
        target = 0; row0 = blockIdx.x * TILE; M = N; xin = hin; yout = out;
    } else {
        target = 1; row0 = (blockIdx.x - nblk) * TILE; M = E; xin = ein;
        yout = out + (size_t)N * D;
    }

    // resident weights: this lane's column pair (2*lane, 2*lane+1)
    unsigned long long w0[32], w1[32];
    {
        const unsigned long long* Wp = &g_Wp[isL2][0][0];
#pragma unroll
        for (int kp = 0; kp < 32; ++kp) {
            w0[kp] = __ldg(&Wp[kp * 64 + 2 * lane]);
            w1[kp] = __ldg(&Wp[kp * 64 + 2 * lane + 1]);
        }
    }
    const float* bias = isL2 ? b2 : b1;
    float ba = __ldg(&bias[2 * lane]);
    float bb = __ldg(&bias[2 * lane + 1]);
    float epsv = (target == 0) ? (1.f + __ldg(&epsp[0])) : 1.f;

    float cs0 = 0.f, cs1 = 0.f, cq0 = 0.f, cq1 = 0.f;

    // ---- prologue: load chunk 0 ----
    {
        unsigned long long* xb = xs;   // buf 0
        for (int idx = tid; idx < CH * 16; idx += 256) {
            int r = idx >> 4;
            int c4 = idx & 15;
            int gr = row0 + r;
            float4 v = make_float4(0.f, 0.f, 0.f, 0.f);
            if (gr < M) {
                if (target == 0) {
                    float4 a = __ldg((const float4*)(xin + (size_t)gr * D) + c4);
                    float4 n = *((const float4*)(g_neigh + (size_t)gr * D) + c4);
                    v.x = fmaf(epsv, a.x, n.x); v.y = fmaf(epsv, a.y, n.y);
                    v.z = fmaf(epsv, a.z, n.z); v.w = fmaf(epsv, a.w, n.w);
                } else {
                    v = __ldg((const float4*)(xin + (size_t)gr * D) + c4);
                }
            }
            xb[(2 * c4) * TS + r] = pack64(v.x, v.y);
            xb[(2 * c4 + 1) * TS + r] = pack64(v.z, v.w);
        }
    }
    __syncthreads();

    // ---- pipelined steps ----
    for (int s = 0; s <= NSTEP; ++s) {
        // prefetch chunk s+1
        if (s + 1 < NSTEP) {
            int base = row0 + (s + 1) * CH;
            unsigned long long* xb = xs + ((s + 1) & 1) * 32 * TS;
            for (int idx = tid; idx < CH * 16; idx += 256) {
                int r = idx >> 4;
                int c4 = idx & 15;
                int gr = base + r;
                float4 v = make_float4(0.f, 0.f, 0.f, 0.f);
                if (gr < M) {
                    if (target == 0) {
                        float4 a = __ldg((const float4*)(xin + (size_t)gr * D) + c4);
                        float4 n = *((const float4*)(g_neigh + (size_t)gr * D) + c4);
                        v.x = fmaf(epsv, a.x, n.x); v.y = fmaf(epsv, a.y, n.y);
                        v.z = fmaf(epsv, a.z, n.z); v.w = fmaf(epsv, a.w, n.w);
                    } else {
                        v = __ldg((const float4*)(xin + (size_t)gr * D) + c4);
                    }
                }
                xb[(2 * c4) * TS + r] = pack64(v.x, v.y);
                xb[(2 * c4 + 1) * TS + r] = pack64(v.z, v.w);
            }
        }

        if (!isL2) {
            // layer 1 on chunk s
            if (s < NSTEP) {
                const unsigned long long* xb = xs + (s & 1) * 32 * TS;
                unsigned long long* tb = ts + (s & 1) * 32 * TS;
#pragma unroll 2
                for (int rr = 0; rr < 16; ++rr) {
                    int r = wsub * 16 + rr;
                    unsigned long long a0 = 0ull, a1 = 0ull;
#pragma unroll
                    for (int kp = 0; kp < 32; ++kp) {
                        unsigned long long xv = xb[kp * TS + r];   // broadcast
                        a0 = fma2(xv, w0[kp], a0);
                        a1 = fma2(xv, w1[kp], a1);
                    }
                    float lo, hi;
                    unpack2(a0, lo, hi);
                    float t0 = fmaxf(lo + hi + ba, 0.f);
                    unpack2(a1, lo, hi);
                    float t1 = fmaxf(lo + hi + bb, 0.f);
                    tb[lane * TS + r] = pack64(t0, t1);
                }
            }
        } else {
            // layer 2 on chunk s-1
            if (s >= 1) {
                int sc = s - 1;
                int base = row0 + sc * CH;
                const unsigned long long* tb = ts + (sc & 1) * 32 * TS;
#pragma unroll 2
                for (int rr = 0; rr < 16; ++rr) {
                    int r = wsub * 16 + rr;
                    int gr = base + r;
                    unsigned long long a0 = 0ull, a1 = 0ull;
#pragma unroll
                    for (int kp = 0; kp < 32; ++kp) {
                        unsigned long long tv = tb[kp * TS + r];   // broadcast
                        a0 = fma2(tv, w0[kp], a0);
                        a1 = fma2(tv, w1[kp], a1);
                    }
                    float lo, hi;
                    unpack2(a0, lo, hi);
                    float y0 = lo + hi + ba;
                    unpack2(a1, lo, hi);
                    float y1 = lo + hi + bb;
                    if (gr < M) {
                        *(float2*)(yout + (size_t)gr * D + 2 * lane) = make_float2(y0, y1);
                        cs0 += y0; cq0 += y0 * y0;
                        cs1 += y1; cq1 += y1 * y1;
                    }
                }
            }
        }
        __syncthreads();
    }

    // ---- stats: L2 threads hold per-column partials ----
    if (isL2) {
        int rep = ((blockIdx.x << 2) | wsub) & (NREP - 1);
        atomicAdd(&g_sum[target][rep][2 * lane], cs0);
        atomicAdd(&g_sum[target][rep][2 * lane + 1], cs1);
        atomicAdd(&g_sq[target][rep][2 * lane], cq0);
        atomicAdd(&g_sq[target][rep][2 * lane + 1], cq1);
    }
}

// ---------------- K3: finalize mean / rstd ----------------
__global__ void stats_kernel(int N, int E) {
    int t = threadIdx.x;
    int target = t >> 6;
    int c = t & 63;
    float s = 0.f, q = 0.f;
#pragma unroll
    for (int r = 0; r < NREP; ++r) { s += g_sum[target][r][c]; q += g_sq[target][r][c]; }
    float cnt = target ? (float)E : (float)N;
    float m = s / cnt;
    float var = q / cnt - m * m;
    g_mean[target][c] = m;
    g_rstd[target][c] = rsqrtf(var + 1e-5f);
}

// ---------------- K4/K5: normalize + relu + residual ----------------
__global__ void apply_kernel(const float* __restrict__ res,
                             const float* __restrict__ gamma,
                             const float* __restrict__ beta,
                             float* __restrict__ y, int M, int target) {
    int idx = blockIdx.x * blockDim.x + threadIdx.x;
    int total = M * 16;
    if (idx >= total) return;
    int r = idx >> 4;
    int c4 = idx & 15;
    size_t off = (size_t)r * D + c4 * 4;
    float4 v = *(float4*)(y + off);
    float4 rs = __ldg((const float4*)res + (off >> 2));
    float4 g = __ldg((const float4*)gamma + c4);
    float4 b = __ldg((const float4*)beta + c4);
    int c = c4 * 4;
    float4 m = *(const float4*)&g_mean[target][c];
    float4 sd = *(const float4*)&g_rstd[target][c];
    float4 o;
    o.x = rs.x + fmaxf(g.x * (v.x - m.x) * sd.x + b.x, 0.f);
    o.y = rs.y + fmaxf(g.y * (v.y - m.y) * sd.y + b.y, 0.f);
    o.z = rs.z + fmaxf(g.z * (v.z - m.z) * sd.z + b.z, 0.f);
    o.w = rs.w + fmaxf(g.w * (v.w - m.w) * sd.w + b.w, 0.f);
    *(float4*)(y + off) = o;
}

// ---------------- launcher ----------------
extern "C" void kernel_launch(void* const* d_in, const int* in_sizes, int n_in,
                              void* d_out, int out_size) {
    const float* h   = (const float*)d_in[0];
    const float* e   = (const float*)d_in[1];
    const int*   src = (const int*)d_in[2];
    const int*   dst = (const int*)d_in[3];
    const float* eps = (const float*)d_in[4];
    const float* W1  = (const float*)d_in[5];
    const float* b1  = (const float*)d_in[6];
    const float* W2  = (const float*)d_in[7];
    const float* b2  = (const float*)d_in[8];
    const float* gh  = (const float*)d_in[9];
    const float* bh  = (const float*)d_in[10];
    const float* ge  = (const float*)d_in[11];
    const float* be  = (const float*)d_in[12];

    int N = in_sizes[0] / D;
    int E = in_sizes[1] / D;
    float* out_h = (float*)d_out;
    float* out_e = out_h + (size_t)N * D;

    cudaFuncSetAttribute(mlp_ws_kernel, cudaFuncAttributeMaxDynamicSharedMemorySize, SMEM_BYTES);

    zero_kernel<<<1024, 256>>>(W1, W2);
    scatter_kernel<<<(E * 16 + 255) / 256, 256>>>(h, src, dst, E);

    int nblk = (N + TILE - 1) / TILE;
    int eblk = (E + TILE - 1) / TILE;
    mlp_ws_kernel<<<nblk + eblk, 256, SMEM_BYTES>>>(h, e, eps, b1, b2, out_h, N, E, nblk);

    stats_kernel<<<1, 128>>>(N, E);

    apply_kernel<<<(N * 16 + 255) / 256, 256>>>(h, gh, bh, out_h, N, 0);
    apply_kernel<<<(E * 16 + 255) / 256, 256>>>(e, ge, be, out_e, E, 1);
}

// round 9
// speedup vs baseline: 1.8314x; 1.0470x over previous
#include <cuda_runtime.h>
#include <cuda_bf16.h>
#include <cstdint>

#define D 64
#define CH 32              // rows per pipeline chunk
#define TILE 512           // rows per CTA
#define NSTEP (TILE / CH)  // 16
#define XS 34              // u64 stride per row (32 data + 2 pad, 16B-aligned)
#define NREP 64
#define MAX_N 100000

// ---------------- scratch (device globals) ----------------
__device__ float g_neigh[MAX_N * D];
__device__ float g_sum[2][NREP][D];
__device__ float g_sq[2][NREP][D];
__device__ __align__(16) float g_mean[2][D];
__device__ __align__(16) float g_rstd[2][D];
// k-paired weights: g_Wp[layer][kw][c] = (W[2kw][c], W[2kw+1][c])
__device__ unsigned long long g_Wp[2][32][64];

// ---------------- packed fp32x2 helpers ----------------
__device__ __forceinline__ unsigned long long pack64(float lo, float hi) {
    unsigned long long r;
    asm("mov.b64 %0, {%1, %2};" : "=l"(r) : "f"(lo), "f"(hi));
    return r;
}
__device__ __forceinline__ void unpack2(unsigned long long v, float& lo, float& hi) {
    asm("mov.b64 {%0, %1}, %2;" : "=f"(lo), "=f"(hi) : "l"(v));
}
__device__ __forceinline__ unsigned long long fma2(unsigned long long a,
                                                   unsigned long long b,
                                                   unsigned long long c) {
    unsigned long long d;
    asm("fma.rn.f32x2 %0, %1, %2, %3;" : "=l"(d) : "l"(a), "l"(b), "l"(c));
    return d;
}

// ---------------- K0a: zero neigh ----------------
__global__ void zero_neigh_kernel() {
    int tid = blockIdx.x * blockDim.x + threadIdx.x;
    int stride = gridDim.x * blockDim.x;
    float4* p = (float4*)g_neigh;
    const int n4 = MAX_N * D / 4;
    for (int i = tid; i < n4; i += stride) p[i] = make_float4(0.f, 0.f, 0.f, 0.f);
}
// ---------------- K0b: zero stats ----------------
__global__ void zero_stats_kernel() {
    int tid = blockIdx.x * blockDim.x + threadIdx.x;
    float* s = &g_sum[0][0][0];
    float* q = &g_sq[0][0][0];
    const int ns = 2 * NREP * D;
    if (tid < ns) { s[tid] = 0.f; q[tid] = 0.f; }
}
// ---------------- K0c: build k-paired W ----------------
__global__ void build_w_kernel(const float* __restrict__ W1, const float* __restrict__ W2) {
    int i = blockIdx.x * blockDim.x + threadIdx.x;
    if (i >= 2 * 32 * 64) return;
    int layer = i >> 11;
    int kw = (i >> 6) & 31;
    int c = i & 63;
    const float* W = layer ? W2 : W1;
    g_Wp[layer][kw][c] = pack64(__ldg(&W[(2 * kw) * D + c]),
                                __ldg(&W[(2 * kw + 1) * D + c]));
}

// ---------------- K1: scatter-sum  neigh[dst] += h[src] (half range) ----------------
__global__ void scatter_kernel(const float* __restrict__ h,
                               const int* __restrict__ src,
                               const int* __restrict__ dst, int e0, int e1) {
    int idx = blockIdx.x * blockDim.x + threadIdx.x;
    int total = (e1 - e0) * 16;
    if (idx >= total) return;
    int e = e0 + (idx >> 4);
    int c = idx & 15;
    int s = __ldg(&src[e]);
    int d = __ldg(&dst[e]);
    float4 v = __ldg((const float4*)(h + (size_t)s * D) + c);
    float* p = g_neigh + (size_t)d * D + c * 4;
    asm volatile("red.global.add.v4.f32 [%0], {%1, %2, %3, %4};"
                 :: "l"(p), "f"(v.x), "f"(v.y), "f"(v.z), "f"(v.w) : "memory");
}

// fill one chunk of x into smem buffer (row-major u64 pairs)
__device__ __forceinline__ void fill_chunk(unsigned long long* xb,
                                           const float* __restrict__ xin,
                                           int base, int M, int target, float epsv,
                                           int tid) {
    for (int idx = tid; idx < CH * 16; idx += 256) {
        int r = idx >> 4;
        int c4 = idx & 15;
        int gr = base + r;
        float4 v = make_float4(0.f, 0.f, 0.f, 0.f);
        if (gr < M) {
            if (target == 0) {
                float4 a = __ldg((const float4*)(xin + (size_t)gr * D) + c4);
                float4 n = *((const float4*)(g_neigh + (size_t)gr * D) + c4);
                v.x = fmaf(epsv, a.x, n.x); v.y = fmaf(epsv, a.y, n.y);
                v.z = fmaf(epsv, a.z, n.z); v.w = fmaf(epsv, a.w, n.w);
            } else {
                v = __ldg((const float4*)(xin + (size_t)gr * D) + c4);
            }
        }
        ulonglong2 pk;
        pk.x = pack64(v.x, v.y);
        pk.y = pack64(v.z, v.w);
        *(ulonglong2*)&xb[r * XS + 2 * c4] = pk;
    }
}

// ---------------- K2: weight-stationary warp-specialized MLP (2 CTA/SM) ----------------
__global__ void __launch_bounds__(256, 2)
mlp_ws_kernel(const float* __restrict__ hin, const float* __restrict__ ein,
              const float* __restrict__ epsp,
              const float* __restrict__ b1, const float* __restrict__ b2,
              float* __restrict__ out, int N, int E, int nblk) {
    __shared__ unsigned long long xs[2][CH * XS];
    __shared__ unsigned long long ts[2][CH * XS];

    int tid = threadIdx.x;
    int wid = tid >> 5;
    int lane = tid & 31;
    int isL2 = wid >> 2;       // warps 0-3: layer1, warps 4-7: layer2
    int wsub = wid & 3;
    int colh = wsub & 1;
    int rowh = wsub >> 1;
    int col = colh * 32 + lane;
    int rbase = rowh * 16;

    int target, row0, M;
    const float* xin;
    float* yout;
    if (blockIdx.x < nblk) {
        target = 0; row0 = blockIdx.x * TILE; M = N; xin = hin; yout = out;
    } else {
        target = 1; row0 = (blockIdx.x - nblk) * TILE; M = E; xin = ein;
        yout = out + (size_t)N * D;
    }

    // resident weights: this lane's single column
    unsigned long long w[32];
    {
        const unsigned long long* Wp = &g_Wp[isL2][0][0];
#pragma unroll
        for (int kw = 0; kw < 32; ++kw) w[kw] = __ldg(&Wp[kw * 64 + col]);
    }
    float bias = __ldg(&((isL2 ? b2 : b1)[col]));
    float epsv = (target == 0) ? (1.f + __ldg(&epsp[0])) : 1.f;

    float cs = 0.f, cq = 0.f;

    fill_chunk(xs[0], xin, row0, M, target, epsv, tid);
    __syncthreads();

    for (int s = 0; s <= NSTEP; ++s) {
        if (s + 1 < NSTEP)
            fill_chunk(xs[(s + 1) & 1], xin, row0 + (s + 1) * CH, M, target, epsv, tid);

        if (!isL2) {
            if (s < NSTEP) {
                const unsigned long long* xb = xs[s & 1];
                float* tb = (float*)ts[s & 1];
#pragma unroll
                for (int rr = 0; rr < 16; rr += 2) {
                    int r0 = rbase + rr;
                    int r1 = r0 + 1;
                    unsigned long long a0 = 0ull, a1 = 0ull;
#pragma unroll
                    for (int kc = 0; kc < 16; ++kc) {
                        ulonglong2 x0 = *(const ulonglong2*)&xb[r0 * XS + 2 * kc];
                        ulonglong2 x1 = *(const ulonglong2*)&xb[r1 * XS + 2 * kc];
                        a0 = fma2(x0.x, w[2 * kc], a0);
                        a1 = fma2(x1.x, w[2 * kc], a1);
                        a0 = fma2(x0.y, w[2 * kc + 1], a0);
                        a1 = fma2(x1.y, w[2 * kc + 1], a1);
                    }
                    float lo, hi;
                    unpack2(a0, lo, hi);
                    tb[r0 * (2 * XS) + col] = fmaxf(lo + hi + bias, 0.f);
                    unpack2(a1, lo, hi);
                    tb[r1 * (2 * XS) + col] = fmaxf(lo + hi + bias, 0.f);
                }
            }
        } else {
            if (s >= 1) {
                int sc = s - 1;
                int base = row0 + sc * CH;
                const unsigned long long* tb = ts[sc & 1];
#pragma unroll
                for (int rr = 0; rr < 16; rr += 2) {
                    int r0 = rbase + rr;
                    int r1 = r0 + 1;
                    unsigned long long a0 = 0ull, a1 = 0ull;
#pragma unroll
                    for (int kc = 0; kc < 16; ++kc) {
                        ulonglong2 x0 = *(const ulonglong2*)&tb[r0 * XS + 2 * kc];
                        ulonglong2 x1 = *(const ulonglong2*)&tb[r1 * XS + 2 * kc];
                        a0 = fma2(x0.x, w[2 * kc], a0);
                        a1 = fma2(x1.x, w[2 * kc], a1);
                        a0 = fma2(x0.y, w[2 * kc + 1], a0);
                        a1 = fma2(x1.y, w[2 * kc + 1], a1);
                    }
                    float lo, hi;
                    unpack2(a0, lo, hi);
                    float y0 = lo + hi + bias;
                    unpack2(a1, lo, hi);
                    float y1 = lo + hi + bias;
                    int g0 = base + r0;
                    int g1 = base + r1;
                    if (g0 < M) {
                        yout[(size_t)g0 * D + col] = y0;
                        cs += y0; cq += y0 * y0;
                    }
                    if (g1 < M) {
                        yout[(size_t)g1 * D + col] = y1;
                        cs += y1; cq += y1 * y1;
                    }
                }
            }
        }
        __syncthreads();
    }

    // ---- stats: L2 threads hold per-column partials ----
    if (isL2) {
        int rep = ((blockIdx.x << 1) | rowh) & (NREP - 1);
        atomicAdd(&g_sum[target][rep][col], cs);
        atomicAdd(&g_sq[target][rep][col], cq);
    }
}

// ---------------- K3: finalize mean / rstd ----------------
__global__ void stats_kernel(int N, int E) {
    int t = threadIdx.x;
    int target = t >> 6;
    int c = t & 63;
    float s = 0.f, q = 0.f;
#pragma unroll
    for (int r = 0; r < NREP; ++r) { s += g_sum[target][r][c]; q += g_sq[target][r][c]; }
    float cnt = target ? (float)E : (float)N;
    float m = s / cnt;
    float var = q / cnt - m * m;
    g_mean[target][c] = m;
    g_rstd[target][c] = rsqrtf(var + 1e-5f);
}

// ---------------- K4/K5: normalize + relu + residual ----------------
__global__ void apply_kernel(const float* __restrict__ res,
                             const float* __restrict__ gamma,
                             const float* __restrict__ beta,
                             float* __restrict__ y, int M, int target) {
    int idx = blockIdx.x * blockDim.x + threadIdx.x;
    int total = M * 16;
    if (idx >= total) return;
    int r = idx >> 4;
    int c4 = idx & 15;
    size_t off = (size_t)r * D + c4 * 4;
    float4 v = *(float4*)(y + off);
    float4 rs = __ldg((const float4*)res + (off >> 2));
    float4 g = __ldg((const float4*)gamma + c4);
    float4 b = __ldg((const float4*)beta + c4);
    int c = c4 * 4;
    float4 m = *(const float4*)&g_mean[target][c];
    float4 sd = *(const float4*)&g_rstd[target][c];
    float4 o;
    o.x = rs.x + fmaxf(g.x * (v.x - m.x) * sd.x + b.x, 0.f);
    o.y = rs.y + fmaxf(g.y * (v.y - m.y) * sd.y + b.y, 0.f);
    o.z = rs.z + fmaxf(g.z * (v.z - m.z) * sd.z + b.z, 0.f);
    o.w = rs.w + fmaxf(g.w * (v.w - m.w) * sd.w + b.w, 0.f);
    *(float4*)(y + off) = o;
}

// ---------------- launcher ----------------
extern "C" void kernel_launch(void* const* d_in, const int* in_sizes, int n_in,
                              void* d_out, int out_size) {
    const float* h   = (const float*)d_in[0];
    const float* e   = (const float*)d_in[1];
    const int*   src = (const int*)d_in[2];
    const int*   dst = (const int*)d_in[3];
    const float* eps = (const float*)d_in[4];
    const float* W1  = (const float*)d_in[5];
    const float* b1  = (const float*)d_in[6];
    const float* W2  = (const float*)d_in[7];
    const float* b2  = (const float*)d_in[8];
    const float* gh  = (const float*)d_in[9];
    const float* bh  = (const float*)d_in[10];
    const float* ge  = (const float*)d_in[11];
    const float* be  = (const float*)d_in[12];

    int N = in_sizes[0] / D;
    int E = in_sizes[1] / D;
    float* out_h = (float*)d_out;
    float* out_e = out_h + (size_t)N * D;

    // launch order chosen so the mlp kernel is launch index 5 (ncu -s 5 -c 1)
    zero_neigh_kernel<<<1024, 256>>>();                                   // 0
    zero_stats_kernel<<<(2 * NREP * D + 255) / 256, 256>>>();             // 1
    build_w_kernel<<<(2 * 32 * 64 + 255) / 256, 256>>>(W1, W2);           // 2
    int eh = E / 2;
    scatter_kernel<<<(eh * 16 + 255) / 256, 256>>>(h, src, dst, 0, eh);   // 3
    scatter_kernel<<<((E - eh) * 16 + 255) / 256, 256>>>(h, src, dst, eh, E); // 4

    int nblk = (N + TILE - 1) / TILE;
    int eblk = (E + TILE - 1) / TILE;
    mlp_ws_kernel<<<nblk + eblk, 256>>>(h, e, eps, b1, b2, out_h, N, E, nblk); // 5

    stats_kernel<<<1, 128>>>(N, E);                                       // 6

    apply_kernel<<<(N * 16 + 255) / 256, 256>>>(h, gh, bh, out_h, N, 0);  // 7
    apply_kernel<<<(E * 16 + 255) / 256, 256>>>(e, ge, be, out_e, E, 1);  // 8
}

// round 10
// speedup vs baseline: 2.0365x; 1.1120x over previous
#include <cuda_runtime.h>
#include <cuda_bf16.h>
#include <cstdint>

#define D 64
#define CH 32              // rows per pipeline chunk
#define TILE 512           // rows per CTA
#define NSTEP (TILE / CH)  // 16
#define XS 34              // u64 stride per row (32 data + 2 pad, 16B-aligned)
#define NREP 64
#define MAX_N 100000

// ---------------- scratch (device globals) ----------------
__device__ float g_neigh[MAX_N * D];
__device__ float g_sum[2][NREP][D];
__device__ float g_sq[2][NREP][D];
__device__ __align__(16) float g_mean[2][D];
__device__ __align__(16) float g_rstd[2][D];
// k-paired weights: g_Wp[layer][kw][c] = (W[2kw][c], W[2kw+1][c])
__device__ unsigned long long g_Wp[2][32][64];

// ---------------- packed fp32x2 helpers ----------------
__device__ __forceinline__ unsigned long long pack64(float lo, float hi) {
    unsigned long long r;
    asm("mov.b64 %0, {%1, %2};" : "=l"(r) : "f"(lo), "f"(hi));
    return r;
}
__device__ __forceinline__ void unpack2(unsigned long long v, float& lo, float& hi) {
    asm("mov.b64 {%0, %1}, %2;" : "=f"(lo), "=f"(hi) : "l"(v));
}
__device__ __forceinline__ unsigned long long fma2(unsigned long long a,
                                                   unsigned long long b,
                                                   unsigned long long c) {
    unsigned long long d;
    asm("fma.rn.f32x2 %0, %1, %2, %3;" : "=l"(d) : "l"(a), "l"(b), "l"(c));
    return d;
}
__device__ __forceinline__ uint32_t s2u(const void* p) {
    uint32_t a;
    asm("{ .reg .u64 t; cvta.to.shared.u64 t, %1; cvt.u32.u64 %0, t; }" : "=r"(a) : "l"(p));
    return a;
}

// ---------------- K0: zero neigh + build k-paired W ----------------
__global__ void init_kernel(const float* __restrict__ W1, const float* __restrict__ W2) {
    int tid = blockIdx.x * blockDim.x + threadIdx.x;
    int stride = gridDim.x * blockDim.x;
    float4* p = (float4*)g_neigh;
    const int n4 = MAX_N * D / 4;
    for (int i = tid; i < n4; i += stride) p[i] = make_float4(0.f, 0.f, 0.f, 0.f);
    for (int i = tid; i < 2 * 32 * 64; i += stride) {
        int layer = i >> 11;
        int kw = (i >> 6) & 31;
        int c = i & 63;
        const float* W = layer ? W2 : W1;
        g_Wp[layer][kw][c] = pack64(__ldg(&W[(2 * kw) * D + c]),
                                    __ldg(&W[(2 * kw + 1) * D + c]));
    }
}

// ---------------- K1: scatter-sum  neigh[dst] += h[src] ----------------
__global__ void scatter_kernel(const float* __restrict__ h,
                               const int* __restrict__ src,
                               const int* __restrict__ dst, int E) {
    int idx = blockIdx.x * blockDim.x + threadIdx.x;
    int total = E * 16;
    if (idx >= total) return;
    int e = idx >> 4;
    int c = idx & 15;
    int s = __ldg(&src[e]);
    int d = __ldg(&dst[e]);
    float4 v = __ldg((const float4*)(h + (size_t)s * D) + c);
    float* p = g_neigh + (size_t)d * D + c * 4;
    asm volatile("red.global.add.v4.f32 [%0], {%1, %2, %3, %4};"
                 :: "l"(p), "f"(v.x), "f"(v.y), "f"(v.z), "f"(v.w) : "memory");
}

// ---------------- K2: combine hn = (1+eps)h + neigh into g_neigh; zero stats ----------------
__global__ void combine_kernel(const float* __restrict__ h,
                               const float* __restrict__ epsp, int N) {
    int idx = blockIdx.x * blockDim.x + threadIdx.x;
    if (idx < 2 * NREP * D) {
        (&g_sum[0][0][0])[idx] = 0.f;
        (&g_sq[0][0][0])[idx] = 0.f;
    }
    if (idx >= N * 16) return;
    float epsv = 1.f + __ldg(&epsp[0]);
    float4 a = __ldg((const float4*)h + idx);
    float4* pn = (float4*)g_neigh + idx;
    float4 n = *pn;
    n.x = fmaf(epsv, a.x, n.x);
    n.y = fmaf(epsv, a.y, n.y);
    n.z = fmaf(epsv, a.z, n.z);
    n.w = fmaf(epsv, a.w, n.w);
    *pn = n;
}

// async fill of one chunk (cp.async, zero-fill OOB tail)
__device__ __forceinline__ void fill_async(unsigned long long* xb,
                                           const float* __restrict__ xsrc,
                                           int base, int M, int tid) {
#pragma unroll
    for (int t = 0; t < 2; ++t) {
        int idx = tid + t * 256;
        int r = idx >> 4;
        int c4 = idx & 15;
        int gr = base + r;
        unsigned long long* sp = &xb[r * XS + 2 * c4];
        if (gr < M) {
            uint32_t sa = s2u(sp);
            const float4* ga = (const float4*)(xsrc + (size_t)gr * D) + c4;
            asm volatile("cp.async.ca.shared.global [%0], [%1], 16;"
                         :: "r"(sa), "l"(ga) : "memory");
        } else {
            *(ulonglong2*)sp = make_ulonglong2(0ull, 0ull);
        }
    }
}

// ---------------- K3: weight-stationary warp-specialized MLP (2 CTA/SM) ----------------
__global__ void __launch_bounds__(256, 2)
mlp_ws_kernel(const float* __restrict__ ein,
              const float* __restrict__ b1, const float* __restrict__ b2,
              float* __restrict__ out, int N, int E, int nblk) {
    __shared__ unsigned long long xs[2][CH * XS];
    __shared__ unsigned long long ts[2][CH * XS];

    int tid = threadIdx.x;
    int wid = tid >> 5;
    int lane = tid & 31;
    int isL2 = wid >> 2;       // warps 0-3: layer1, warps 4-7: layer2
    int wsub = wid & 3;
    int colh = wsub & 1;
    int rowh = wsub >> 1;
    int col = colh * 32 + lane;
    int rbase = rowh * 16;

    int target, row0, M;
    const float* xsrc;
    float* yout;
    if (blockIdx.x < nblk) {
        target = 0; row0 = blockIdx.x * TILE; M = N; xsrc = g_neigh; yout = out;
    } else {
        target = 1; row0 = (blockIdx.x - nblk) * TILE; M = E; xsrc = ein;
        yout = out + (size_t)N * D;
    }

    // resident weights: this lane's single column
    unsigned long long w[32];
    {
        const unsigned long long* Wp = &g_Wp[isL2][0][0];
#pragma unroll
        for (int kw = 0; kw < 32; ++kw) w[kw] = __ldg(&Wp[kw * 64 + col]);
    }
    float bias = __ldg(&((isL2 ? b2 : b1)[col]));

    float cs = 0.f, cq = 0.f;

    fill_async(xs[0], xsrc, row0, M, tid);
    asm volatile("cp.async.commit_group;" ::: "memory");

    for (int s = 0; s <= NSTEP; ++s) {
        if (s + 1 < NSTEP)
            fill_async(xs[(s + 1) & 1], xsrc, row0 + (s + 1) * CH, M, tid);
        asm volatile("cp.async.commit_group;" ::: "memory");
        asm volatile("cp.async.wait_group 1;" ::: "memory");
        __syncthreads();

        if (!isL2) {
            if (s < NSTEP) {
                const unsigned long long* xb = xs[s & 1];
                float* tb = (float*)ts[s & 1];
#pragma unroll
                for (int rr = 0; rr < 16; rr += 2) {
                    int r0 = rbase + rr;
                    int r1 = r0 + 1;
                    unsigned long long a0 = 0ull, a1 = 0ull;
#pragma unroll
                    for (int kc = 0; kc < 16; ++kc) {
                        ulonglong2 x0 = *(const ulonglong2*)&xb[r0 * XS + 2 * kc];
                        ulonglong2 x1 = *(const ulonglong2*)&xb[r1 * XS + 2 * kc];
                        a0 = fma2(x0.x, w[2 * kc], a0);
                        a1 = fma2(x1.x, w[2 * kc], a1);
                        a0 = fma2(x0.y, w[2 * kc + 1], a0);
                        a1 = fma2(x1.y, w[2 * kc + 1], a1);
                    }
                    float lo, hi;
                    unpack2(a0, lo, hi);
                    tb[r0 * (2 * XS) + col] = fmaxf(lo + hi + bias, 0.f);
                    unpack2(a1, lo, hi);
                    tb[r1 * (2 * XS) + col] = fmaxf(lo + hi + bias, 0.f);
                }
            }
        } else {
            if (s >= 1) {
                int sc = s - 1;
                int base = row0 + sc * CH;
                const unsigned long long* tb = ts[sc & 1];
#pragma unroll
                for (int rr = 0; rr < 16; rr += 2) {
                    int r0 = rbase + rr;
                    int r1 = r0 + 1;
                    unsigned long long a0 = 0ull, a1 = 0ull;
#pragma unroll
                    for (int kc = 0; kc < 16; ++kc) {
                        ulonglong2 x0 = *(const ulonglong2*)&tb[r0 * XS + 2 * kc];
                        ulonglong2 x1 = *(const ulonglong2*)&tb[r1 * XS + 2 * kc];
                        a0 = fma2(x0.x, w[2 * kc], a0);
                        a1 = fma2(x1.x, w[2 * kc], a1);
                        a0 = fma2(x0.y, w[2 * kc + 1], a0);
                        a1 = fma2(x1.y, w[2 * kc + 1], a1);
                    }
                    float lo, hi;
                    unpack2(a0, lo, hi);
                    float y0 = lo + hi + bias;
                    unpack2(a1, lo, hi);
                    float y1 = lo + hi + bias;
                    int g0 = base + r0;
                    int g1 = base + r1;
                    if (g0 < M) {
                        yout[(size_t)g0 * D + col] = y0;
                        cs += y0; cq += y0 * y0;
                    }
                    if (g1 < M) {
                        yout[(size_t)g1 * D + col] = y1;
                        cs += y1; cq += y1 * y1;
                    }
                }
            }
        }
        __syncthreads();
    }

    // ---- stats: L2 threads hold per-column partials ----
    if (isL2) {
        int rep = ((blockIdx.x << 1) | rowh) & (NREP - 1);
        atomicAdd(&g_sum[target][rep][col], cs);
        atomicAdd(&g_sq[target][rep][col], cq);
    }
}

// ---------------- K4: finalize mean / rstd ----------------
__global__ void stats_kernel(int N, int E) {
    int t = threadIdx.x;
    int target = t >> 6;
    int c = t & 63;
    float s = 0.f, q = 0.f;
#pragma unroll
    for (int r = 0; r < NREP; ++r) { s += g_sum[target][r][c]; q += g_sq[target][r][c]; }
    float cnt = target ? (float)E : (float)N;
    float m = s / cnt;
    float var = q / cnt - m * m;
    g_mean[target][c] = m;
    g_rstd[target][c] = rsqrtf(var + 1e-5f);
}

// ---------------- K5/K6: normalize + relu + residual ----------------
__global__ void apply_kernel(const float* __restrict__ res,
                             const float* __restrict__ gamma,
                             const float* __restrict__ beta,
                             float* __restrict__ y, int M, int target) {
    int idx = blockIdx.x * blockDim.x + threadIdx.x;
    int total = M * 16;
    if (idx >= total) return;
    int r = idx >> 4;
    int c4 = idx & 15;
    size_t off = (size_t)r * D + c4 * 4;
    float4 v = *(float4*)(y + off);
    float4 rs = __ldg((const float4*)res + (off >> 2));
    float4 g = __ldg((const float4*)gamma + c4);
    float4 b = __ldg((const float4*)beta + c4);
    int c = c4 * 4;
    float4 m = *(const float4*)&g_mean[target][c];
    float4 sd = *(const float4*)&g_rstd[target][c];
    float4 o;
    o.x = rs.x + fmaxf(g.x * (v.x - m.x) * sd.x + b.x, 0.f);
    o.y = rs.y + fmaxf(g.y * (v.y - m.y) * sd.y + b.y, 0.f);
    o.z = rs.z + fmaxf(g.z * (v.z - m.z) * sd.z + b.z, 0.f);
    o.w = rs.w + fmaxf(g.w * (v.w - m.w) * sd.w + b.w, 0.f);
    *(float4*)(y + off) = o;
}

// ---------------- launcher ----------------
extern "C" void kernel_launch(void* const* d_in, const int* in_sizes, int n_in,
                              void* d_out, int out_size) {
    const float* h   = (const float*)d_in[0];
    const float* e   = (const float*)d_in[1];
    const int*   src = (const int*)d_in[2];
    const int*   dst = (const int*)d_in[3];
    const float* eps = (const float*)d_in[4];
    const float* W1  = (const float*)d_in[5];
    const float* b1  = (const float*)d_in[6];
    const float* W2  = (const float*)d_in[7];
    const float* b2  = (const float*)d_in[8];
    const float* gh  = (const float*)d_in[9];
    const float* bh  = (const float*)d_in[10];
    const float* ge  = (const float*)d_in[11];
    const float* be  = (const float*)d_in[12];

    int N = in_sizes[0] / D;
    int E = in_sizes[1] / D;
    float* out_h = (float*)d_out;
    float* out_e = out_h + (size_t)N * D;

    init_kernel<<<1024, 256>>>(W1, W2);                                   // 0
    scatter_kernel<<<(E * 16 + 255) / 256, 256>>>(h, src, dst, E);        // 1
    combine_kernel<<<(N * 16 + 255) / 256, 256>>>(h, eps, N);             // 2

    int nblk = (N + TILE - 1) / TILE;
    int eblk = (E + TILE - 1) / TILE;
    mlp_ws_kernel<<<nblk + eblk, 256>>>(e, b1, b2, out_h, N, E, nblk);    // 3

    stats_kernel<<<1, 128>>>(N, E);                                       // 4

    apply_kernel<<<(N * 16 + 255) / 256, 256>>>(h, gh, bh, out_h, N, 0);  // 5
    apply_kernel<<<(E * 16 + 255) / 256, 256>>>(e, ge, be, out_e, E, 1);  // 6
}

// round 11
// speedup vs baseline: 2.3749x; 1.1662x over previous
#include <cuda_runtime.h>
#include <cuda_bf16.h>
#include <cstdint>

#define D 64
#define CH 64              // rows per pipeline chunk
#define TILE 1024          // rows per CTA
#define NSTEP (TILE / CH)  // 16
#define XS 34              // u64 stride per row (32 data + 2 pad, 16B-aligned)
#define NREP 64
#define MAX_N 100000

// ---------------- scratch (device globals) ----------------
__device__ float g_neigh[MAX_N * D];
__device__ float g_sum[2][NREP][D];
__device__ float g_sq[2][NREP][D];
__device__ __align__(16) float g_mean[2][D];
__device__ __align__(16) float g_rstd[2][D];
// k-paired weights: g_Wp[layer][kw][c] = (W[2kw][c], W[2kw+1][c])
__device__ unsigned long long g_Wp[2][32][64];

// ---------------- packed fp32x2 helpers ----------------
__device__ __forceinline__ unsigned long long pack64(float lo, float hi) {
    unsigned long long r;
    asm("mov.b64 %0, {%1, %2};" : "=l"(r) : "f"(lo), "f"(hi));
    return r;
}
__device__ __forceinline__ void unpack2(unsigned long long v, float& lo, float& hi) {
    asm("mov.b64 {%0, %1}, %2;" : "=f"(lo), "=f"(hi) : "l"(v));
}
__device__ __forceinline__ unsigned long long fma2(unsigned long long a,
                                                   unsigned long long b,
                                                   unsigned long long c) {
    unsigned long long d;
    asm("fma.rn.f32x2 %0, %1, %2, %3;" : "=l"(d) : "l"(a), "l"(b), "l"(c));
    return d;
}
__device__ __forceinline__ uint32_t s2u(const void* p) {
    uint32_t a;
    asm("{ .reg .u64 t; cvta.to.shared.u64 t, %1; cvt.u32.u64 %0, t; }" : "=r"(a) : "l"(p));
    return a;
}

// ---------------- K0: zero neigh + build k-paired W ----------------
__global__ void init_kernel(const float* __restrict__ W1, const float* __restrict__ W2) {
    int tid = blockIdx.x * blockDim.x + threadIdx.x;
    int stride = gridDim.x * blockDim.x;
    float4* p = (float4*)g_neigh;
    const int n4 = MAX_N * D / 4;
    for (int i = tid; i < n4; i += stride) p[i] = make_float4(0.f, 0.f, 0.f, 0.f);
    for (int i = tid; i < 2 * 32 * 64; i += stride) {
        int layer = i >> 11;
        int kw = (i >> 6) & 31;
        int c = i & 63;
        const float* W = layer ? W2 : W1;
        g_Wp[layer][kw][c] = pack64(__ldg(&W[(2 * kw) * D + c]),
                                    __ldg(&W[(2 * kw + 1) * D + c]));
    }
}

// ---------------- K1: scatter-sum  neigh[dst] += h[src] ----------------
__global__ void scatter_kernel(const float* __restrict__ h,
                               const int* __restrict__ src,
                               const int* __restrict__ dst, int E) {
    int idx = blockIdx.x * blockDim.x + threadIdx.x;
    int total = E * 16;
    if (idx >= total) return;
    int e = idx >> 4;
    int c = idx & 15;
    int s = __ldg(&src[e]);
    int d = __ldg(&dst[e]);
    float4 v = __ldg((const float4*)(h + (size_t)s * D) + c);
    float* p = g_neigh + (size_t)d * D + c * 4;
    asm volatile("red.global.add.v4.f32 [%0], {%1, %2, %3, %4};"
                 :: "l"(p), "f"(v.x), "f"(v.y), "f"(v.z), "f"(v.w) : "memory");
}

// ---------------- K2: combine hn = (1+eps)h + neigh into g_neigh; zero stats ----------------
__global__ void combine_kernel(const float* __restrict__ h,
                               const float* __restrict__ epsp, int N) {
    int idx = blockIdx.x * blockDim.x + threadIdx.x;
    if (idx < 2 * NREP * D) {
        (&g_sum[0][0][0])[idx] = 0.f;
        (&g_sq[0][0][0])[idx] = 0.f;
    }
    if (idx >= N * 16) return;
    float epsv = 1.f + __ldg(&epsp[0]);
    float4 a = __ldg((const float4*)h + idx);
    float4* pn = (float4*)g_neigh + idx;
    float4 n = *pn;
    n.x = fmaf(epsv, a.x, n.x);
    n.y = fmaf(epsv, a.y, n.y);
    n.z = fmaf(epsv, a.z, n.z);
    n.w = fmaf(epsv, a.w, n.w);
    *pn = n;
}

// async fill of one chunk (cp.async, zero-fill OOB tail)
__device__ __forceinline__ void fill_async(unsigned long long* xb,
                                           const float* __restrict__ xsrc,
                                           int base, int M, int tid) {
#pragma unroll
    for (int t = 0; t < 4; ++t) {
        int idx = tid + t * 256;
        int r = idx >> 4;
        int c4 = idx & 15;
        int gr = base + r;
        unsigned long long* sp = &xb[r * XS + 2 * c4];
        if (gr < M) {
            uint32_t sa = s2u(sp);
            const float4* ga = (const float4*)(xsrc + (size_t)gr * D) + c4;
            asm volatile("cp.async.ca.shared.global [%0], [%1], 16;"
                         :: "r"(sa), "l"(ga) : "memory");
        } else {
            *(ulonglong2*)sp = make_ulonglong2(0ull, 0ull);
        }
    }
}

// ---------------- K3: weight-stationary MLP, 2 cols/thread ----------------
__global__ void __launch_bounds__(256, 1)
mlp_ws_kernel(const float* __restrict__ ein,
              const float* __restrict__ b1, const float* __restrict__ b2,
              float* __restrict__ out, int N, int E, int nblk) {
    __shared__ unsigned long long xs[2][CH * XS];
    __shared__ unsigned long long ts[2][CH * XS];

    int tid = threadIdx.x;
    int wid = tid >> 5;
    int lane = tid & 31;
    int isL2 = wid >> 2;       // warps 0-3: layer1, warps 4-7: layer2
    int wsub = wid & 3;        // row group within layer
    int c0 = 2 * lane;         // this thread's column pair
    int rbase = wsub * 16;     // 16 rows per warp per chunk

    int target, row0, M;
    const float* xsrc;
    float* yout;
    if (blockIdx.x < nblk) {
        target = 0; row0 = blockIdx.x * TILE; M = N; xsrc = g_neigh; yout = out;
    } else {
        target = 1; row0 = (blockIdx.x - nblk) * TILE; M = E; xsrc = ein;
        yout = out + (size_t)N * D;
    }

    // resident weights: columns c0, c0+1
    unsigned long long w0[32], w1[32];
    {
        const unsigned long long* Wp = &g_Wp[isL2][0][0];
#pragma unroll
        for (int kw = 0; kw < 32; ++kw) {
            w0[kw] = __ldg(&Wp[kw * 64 + c0]);
            w1[kw] = __ldg(&Wp[kw * 64 + c0 + 1]);
        }
    }
    const float* bias = isL2 ? b2 : b1;
    float ba = __ldg(&bias[c0]);
    float bb = __ldg(&bias[c0 + 1]);

    float cs0 = 0.f, cs1 = 0.f, cq0 = 0.f, cq1 = 0.f;

    fill_async(xs[0], xsrc, row0, M, tid);
    asm volatile("cp.async.commit_group;" ::: "memory");

    for (int s = 0; s <= NSTEP; ++s) {
        if (s + 1 < NSTEP)
            fill_async(xs[(s + 1) & 1], xsrc, row0 + (s + 1) * CH, M, tid);
        asm volatile("cp.async.commit_group;" ::: "memory");
        asm volatile("cp.async.wait_group 1;" ::: "memory");
        __syncthreads();

        if (!isL2) {
            if (s < NSTEP) {
                const unsigned long long* xb = xs[s & 1];
                float* tb = (float*)ts[s & 1];
#pragma unroll
                for (int rr = 0; rr < 16; rr += 2) {
                    int r0 = rbase + rr;
                    int r1 = r0 + 1;
                    unsigned long long a00 = 0ull, a01 = 0ull, a10 = 0ull, a11 = 0ull;
#pragma unroll
                    for (int kc = 0; kc < 16; ++kc) {
                        ulonglong2 x0 = *(const ulonglong2*)&xb[r0 * XS + 2 * kc];
                        ulonglong2 x1 = *(const ulonglong2*)&xb[r1 * XS + 2 * kc];
                        a00 = fma2(x0.x, w0[2 * kc], a00);
                        a01 = fma2(x0.x, w1[2 * kc], a01);
                        a10 = fma2(x1.x, w0[2 * kc], a10);
                        a11 = fma2(x1.x, w1[2 * kc], a11);
                        a00 = fma2(x0.y, w0[2 * kc + 1], a00);
                        a01 = fma2(x0.y, w1[2 * kc + 1], a01);
                        a10 = fma2(x1.y, w0[2 * kc + 1], a10);
                        a11 = fma2(x1.y, w1[2 * kc + 1], a11);
                    }
                    float lo, hi, t0, t1;
                    unpack2(a00, lo, hi); t0 = fmaxf(lo + hi + ba, 0.f);
                    unpack2(a01, lo, hi); t1 = fmaxf(lo + hi + bb, 0.f);
                    *(float2*)&tb[r0 * (2 * XS) + c0] = make_float2(t0, t1);
                    unpack2(a10, lo, hi); t0 = fmaxf(lo + hi + ba, 0.f);
                    unpack2(a11, lo, hi); t1 = fmaxf(lo + hi + bb, 0.f);
                    *(float2*)&tb[r1 * (2 * XS) + c0] = make_float2(t0, t1);
                }
            }
        } else {
            if (s >= 1) {
                int sc = s - 1;
                int base = row0 + sc * CH;
                const unsigned long long* tb = ts[sc & 1];
#pragma unroll
                for (int rr = 0; rr < 16; rr += 2) {
                    int r0 = rbase + rr;
                    int r1 = r0 + 1;
                    unsigned long long a00 = 0ull, a01 = 0ull, a10 = 0ull, a11 = 0ull;
#pragma unroll
                    for (int kc = 0; kc < 16; ++kc) {
                        ulonglong2 x0 = *(const ulonglong2*)&tb[r0 * XS + 2 * kc];
                        ulonglong2 x1 = *(const ulonglong2*)&tb[r1 * XS + 2 * kc];
                        a00 = fma2(x0.x, w0[2 * kc], a00);
                        a01 = fma2(x0.x, w1[2 * kc], a01);
                        a10 = fma2(x1.x, w0[2 * kc], a10);
                        a11 = fma2(x1.x, w1[2 * kc], a11);
                        a00 = fma2(x0.y, w0[2 * kc + 1], a00);
                        a01 = fma2(x0.y, w1[2 * kc + 1], a01);
                        a10 = fma2(x1.y, w0[2 * kc + 1], a10);
                        a11 = fma2(x1.y, w1[2 * kc + 1], a11);
                    }
                    float lo, hi;
                    float y00, y01, y10, y11;
                    unpack2(a00, lo, hi); y00 = lo + hi + ba;
                    unpack2(a01, lo, hi); y01 = lo + hi + bb;
                    unpack2(a10, lo, hi); y10 = lo + hi + ba;
                    unpack2(a11, lo, hi); y11 = lo + hi + bb;
                    int g0 = base + r0;
                    int g1 = base + r1;
                    if (g0 < M) {
                        *(float2*)(yout + (size_t)g0 * D + c0) = make_float2(y00, y01);
                        cs0 += y00; cq0 += y00 * y00;
                        cs1 += y01; cq1 += y01 * y01;
                    }
                    if (g1 < M) {
                        *(float2*)(yout + (size_t)g1 * D + c0) = make_float2(y10, y11);
                        cs0 += y10; cq0 += y10 * y10;
                        cs1 += y11; cq1 += y11 * y11;
                    }
                }
            }
        }
        __syncthreads();
    }

    // ---- stats: L2 threads hold per-column partials ----
    if (isL2) {
        int rep = ((blockIdx.x << 2) | wsub) & (NREP - 1);
        atomicAdd(&g_sum[target][rep][c0], cs0);
        atomicAdd(&g_sum[target][rep][c0 + 1], cs1);
        atomicAdd(&g_sq[target][rep][c0], cq0);
        atomicAdd(&g_sq[target][rep][c0 + 1], cq1);
    }
}

// ---------------- K4: finalize mean / rstd ----------------
__global__ void stats_kernel(int N, int E) {
    int t = threadIdx.x;
    int target = t >> 6;
    int c = t & 63;
    float s = 0.f, q = 0.f;
#pragma unroll
    for (int r = 0; r < NREP; ++r) { s += g_sum[target][r][c]; q += g_sq[target][r][c]; }
    float cnt = target ? (float)E : (float)N;
    float m = s / cnt;
    float var = q / cnt - m * m;
    g_mean[target][c] = m;
    g_rstd[target][c] = rsqrtf(var + 1e-5f);
}

// ---------------- K5/K6: normalize + relu + residual ----------------
__global__ void apply_kernel(const float* __restrict__ res,
                             const float* __restrict__ gamma,
                             const float* __restrict__ beta,
                             float* __restrict__ y, int M, int target) {
    int idx = blockIdx.x * blockDim.x + threadIdx.x;
    int total = M * 16;
    if (idx >= total) return;
    int r = idx >> 4;
    int c4 = idx & 15;
    size_t off = (size_t)r * D + c4 * 4;
    float4 v = *(float4*)(y + off);
    float4 rs = __ldg((const float4*)res + (off >> 2));
    float4 g = __ldg((const float4*)gamma + c4);
    float4 b = __ldg((const float4*)beta + c4);
    int c = c4 * 4;
    float4 m = *(const float4*)&g_mean[target][c];
    float4 sd = *(const float4*)&g_rstd[target][c];
    float4 o;
    o.x = rs.x + fmaxf(g.x * (v.x - m.x) * sd.x + b.x, 0.f);
    o.y = rs.y + fmaxf(g.y * (v.y - m.y) * sd.y + b.y, 0.f);
    o.z = rs.z + fmaxf(g.z * (v.z - m.z) * sd.z + b.z, 0.f);
    o.w = rs.w + fmaxf(g.w * (v.w - m.w) * sd.w + b.w, 0.f);
    *(float4*)(y + off) = o;
}

// ---------------- launcher ----------------
extern "C" void kernel_launch(void* const* d_in, const int* in_sizes, int n_in,
                              void* d_out, int out_size) {
    const float* h   = (const float*)d_in[0];
    const float* e   = (const float*)d_in[1];
    const int*   src = (const int*)d_in[2];
    const int*   dst = (const int*)d_in[3];
    const float* eps = (const float*)d_in[4];
    const float* W1  = (const float*)d_in[5];
    const float* b1  = (const float*)d_in[6];
    const float* W2  = (const float*)d_in[7];
    const float* b2  = (const float*)d_in[8];
    const float* gh  = (const float*)d_in[9];
    const float* bh  = (const float*)d_in[10];
    const float* ge  = (const float*)d_in[11];
    const float* be  = (const float*)d_in[12];

    int N = in_sizes[0] / D;
    int E = in_sizes[1] / D;
    float* out_h = (float*)d_out;
    float* out_e = out_h + (size_t)N * D;

    init_kernel<<<1024, 256>>>(W1, W2);                                   // 0
    scatter_kernel<<<(E * 16 + 255) / 256, 256>>>(h, src, dst, E);        // 1
    combine_kernel<<<(N * 16 + 255) / 256, 256>>>(h, eps, N);             // 2

    int nblk = (N + TILE - 1) / TILE;
    int eblk = (E + TILE - 1) / TILE;
    mlp_ws_kernel<<<nblk + eblk, 256>>>(e, b1, b2, out_h, N, E, nblk);    // 3

    stats_kernel<<<1, 128>>>(N, E);                                       // 4

    apply_kernel<<<(N * 16 + 255) / 256, 256>>>(h, gh, bh, out_h, N, 0);  // 5
    apply_kernel<<<(E * 16 + 255) / 256, 256>>>(e, ge, be, out_e, E, 1);  // 6
}